// round 4
// baseline (speedup 1.0000x reference)
#include <cuda_runtime.h>

// Shapes (fixed for this problem): X[N,1024], mean[1024], proj[1024,256], protos[256,256]
#define D_IN 1024
#define DP   256
#define CC   256
#define BM   64
#define BK   32
#define NTHREADS 256

__device__ float g_mproj[DP];  // mean @ proj
__device__ float g_p2[CC];     // ||p_c||^2

// ---------- tiny precompute kernel ----------
__global__ void __launch_bounds__(NTHREADS)
proto_precompute(const float* __restrict__ mean,
                 const float* __restrict__ proj,
                 const float* __restrict__ protos) {
    __shared__ float smean[D_IN];
    const int t = threadIdx.x;
    for (int i = t; i < D_IN; i += NTHREADS) smean[i] = mean[i];
    __syncthreads();
    float acc = 0.f;
#pragma unroll 8
    for (int k = 0; k < D_IN; ++k) acc = fmaf(smean[k], proj[k * DP + t], acc);
    g_mproj[t] = acc;
    float s = 0.f;
    const float* p = protos + (size_t)t * DP;
#pragma unroll 8
    for (int d = 0; d < DP; ++d) s = fmaf(p[d], p[d], s);
    g_p2[t] = s;
}

// ---------- packed f32x2 helpers (Blackwell FFMA2) ----------
__device__ __forceinline__ unsigned long long pack2(float lo, float hi) {
    unsigned long long r;
    asm("mov.b64 %0, {%1,%2};" : "=l"(r) : "f"(lo), "f"(hi));
    return r;
}
__device__ __forceinline__ void unpack2(unsigned long long v, float& lo, float& hi) {
    asm("mov.b64 {%0,%1}, %2;" : "=f"(lo), "=f"(hi) : "l"(v));
}
#define FMA2(d, a, b) asm("fma.rn.f32x2 %0, %1, %2, %0;" : "+l"(d) : "l"(a), "l"(b))

// ---------- fused main kernel ----------
// Per CTA: 64 rows. Phase 1: Z = X@proj - mproj (reg-tiled GEMM, K=1024).
// Row norms via warp shuffle; Z kept UNNORMALIZED in SMEM, fold inv into epilogue.
// Phase 2: S = Z @ P^T with P transposed into padded SMEM; score = -sqrt(z2+p2-2*inv*S).
__global__ void __launch_bounds__(NTHREADS, 2)
proto_main(const float* __restrict__ X,
           const float* __restrict__ proj,
           const float* __restrict__ protos,
           float* __restrict__ out, int N) {
    extern __shared__ float smem[];
    float* Zs = smem;                                   // 64*256
    float* As = smem + BM * DP;                         // 64*32
    float* Bs = As + BM * BK;                           // 32*256
    float* Pt = As;                                     // reuse As+Bs: 32*257 fits in 10240
    float* mp_s = smem + BM * DP + BM * BK + BK * DP;   // 256
    float* p2_s = mp_s + DP;                            // 256
    float* z2_s = p2_s + CC;                            // 64
    float* ri_s = z2_s + BM;                            // 64

    const int tid = threadIdx.x;
    const int tx = tid & 31;   // lane
    const int ty = tid >> 5;   // warp 0..7
    const int rowBase = blockIdx.x * BM;

    if (tid < DP) { mp_s[tid] = g_mproj[tid]; p2_s[tid] = g_p2[tid]; }

    unsigned long long acc[8][4];
#pragma unroll
    for (int i = 0; i < 8; ++i)
#pragma unroll
        for (int j = 0; j < 4; ++j) acc[i][j] = 0ull;

    // ================= Phase 1: Z = X @ proj =================
    for (int kb = 0; kb < D_IN; kb += BK) {
        // A tile: 64 rows x 32 k (float4, coalesced)
#pragma unroll
        for (int ii = 0; ii < 2; ++ii) {
            int idx = tid + NTHREADS * ii;          // 0..511
            int lr = idx >> 3, q = idx & 7;
            int gr = rowBase + lr; if (gr >= N) gr = N - 1;
            float4 v = *(const float4*)(X + (size_t)gr * D_IN + kb + q * 4);
            *(float4*)(As + lr * BK + q * 4) = v;
        }
        // B tile: 32 k x 256 cols (float4, coalesced)
#pragma unroll
        for (int ii = 0; ii < 8; ++ii) {
            int idx = tid + NTHREADS * ii;          // 0..2047
            int kr = idx >> 6, q = idx & 63;
            float4 v = *(const float4*)(proj + (size_t)(kb + kr) * DP + q * 4);
            *(float4*)(Bs + kr * DP + q * 4) = v;
        }
        __syncthreads();
#pragma unroll 8
        for (int kk = 0; kk < BK; ++kk) {
            unsigned long long a2[8], b2[4];
#pragma unroll
            for (int i = 0; i < 8; ++i) {
                float a = As[(ty + 8 * i) * BK + kk];   // warp-broadcast
                a2[i] = pack2(a, a);
            }
#pragma unroll
            for (int j = 0; j < 4; ++j)
                b2[j] = pack2(Bs[kk * DP + tx + 64 * j],
                              Bs[kk * DP + tx + 64 * j + 32]);
#pragma unroll
            for (int i = 0; i < 8; ++i)
#pragma unroll
                for (int j = 0; j < 4; ++j) FMA2(acc[i][j], a2[i], b2[j]);
        }
        __syncthreads();
    }

    // Phase-1 epilogue: subtract mproj, stash Z in SMEM, row norms via shuffle
#pragma unroll
    for (int i = 0; i < 8; ++i) {
        const int lr = ty + 8 * i;
        float ss = 0.f;
#pragma unroll
        for (int j = 0; j < 4; ++j) {
            float z0, z1; unpack2(acc[i][j], z0, z1);
            const int c0 = tx + 64 * j, c1 = c0 + 32;
            z0 -= mp_s[c0]; z1 -= mp_s[c1];
            Zs[lr * DP + c0] = z0;
            Zs[lr * DP + c1] = z1;
            ss = fmaf(z0, z0, fmaf(z1, z1, ss));
            acc[i][j] = 0ull;   // re-zero for phase 2
        }
#pragma unroll
        for (int o = 16; o > 0; o >>= 1) ss += __shfl_xor_sync(0xffffffffu, ss, o);
        if (tx == 0) {
            float n = sqrtf(ss);
            float inv = 1.0f / fmaxf(n, 1e-12f);   // matches F.normalize eps
            ri_s[lr] = inv;
            z2_s[lr] = ss * inv * inv;             // ||z_n||^2
        }
    }
    __syncthreads();

    // ================= Phase 2: S = Z @ P^T =================
    const int PTS = DP + 1;  // padded stride 257 -> conflict-free transpose
    for (int db = 0; db < DP; db += BK) {
        // load P[c][db+dd] transposed into Pt[dd][c]
#pragma unroll
        for (int it = 0; it < 32; ++it) {
            int c = it * 8 + ty;
            Pt[tx * PTS + c] = protos[(size_t)c * DP + db + tx];
        }
        __syncthreads();
#pragma unroll 8
        for (int kk = 0; kk < BK; ++kk) {
            unsigned long long a2[8], b2[4];
#pragma unroll
            for (int i = 0; i < 8; ++i) {
                float a = Zs[(ty + 8 * i) * DP + db + kk];  // warp-broadcast
                a2[i] = pack2(a, a);
            }
#pragma unroll
            for (int j = 0; j < 4; ++j)
                b2[j] = pack2(Pt[kk * PTS + tx + 64 * j],
                              Pt[kk * PTS + tx + 64 * j + 32]);
#pragma unroll
            for (int i = 0; i < 8; ++i)
#pragma unroll
                for (int j = 0; j < 4; ++j) FMA2(acc[i][j], a2[i], b2[j]);
        }
        __syncthreads();
    }

    // Final epilogue: score = -sqrt(max(z2 + p2 - 2*inv*S, 0))
#pragma unroll
    for (int i = 0; i < 8; ++i) {
        const int lr = ty + 8 * i;
        const int gr = rowBase + lr;
        if (gr >= N) continue;
        const float inv = ri_s[lr];
        const float z2 = z2_s[lr];
        float* orow = out + (size_t)gr * CC;
#pragma unroll
        for (int j = 0; j < 4; ++j) {
            float s0, s1; unpack2(acc[i][j], s0, s1);
            const int c0 = tx + 64 * j, c1 = c0 + 32;
            float d0 = z2 + p2_s[c0] - 2.0f * inv * s0;
            float d1 = z2 + p2_s[c1] - 2.0f * inv * s1;
            orow[c0] = -sqrtf(fmaxf(d0, 0.f));
            orow[c1] = -sqrtf(fmaxf(d1, 0.f));
        }
    }
}

extern "C" void kernel_launch(void* const* d_in, const int* in_sizes, int n_in,
                              void* d_out, int out_size) {
    const float* X      = (const float*)d_in[0];
    const float* mean   = (const float*)d_in[1];
    const float* proj   = (const float*)d_in[2];
    const float* protos = (const float*)d_in[3];
    float* out = (float*)d_out;

    const int Din = in_sizes[1];            // 1024
    const int N   = in_sizes[0] / Din;      // 32768

    const int SMEM_BYTES = (BM * DP + BM * BK + BK * DP + DP + CC + BM + BM) * 4; // 109056
    cudaFuncSetAttribute(proto_main, cudaFuncAttributeMaxDynamicSharedMemorySize, SMEM_BYTES);

    proto_precompute<<<1, NTHREADS>>>(mean, proj, protos);
    proto_main<<<(N + BM - 1) / BM, NTHREADS, SMEM_BYTES>>>(X, proj, protos, out, N);
}

// round 8
// speedup vs baseline: 4.7315x; 4.7315x over previous
#include <cuda_runtime.h>
#include <cuda_bf16.h>
#include <cstdint>

#define D_IN 1024
#define DP   256
#define CC   256
#define BM   128
#define BK   64
#define NT   512

// padded SMEM row strides (bytes) -> conflict-free ldmatrix without XOR swizzle
#define SA 144    // A/B tiles: 64 bf16 = 128B + 16B pad   (144/4 = 36 ≡ 4 mod 32)
#define SB 144
#define SZ 528    // Z rows: 256 bf16 = 512B + 16B pad     (528/4 = 132 ≡ 4 mod 32)

// smem layout (byte offsets)
#define OFF_A0   0
#define OFF_A1   (OFF_A0 + BM * SA)         // 18432
#define OFF_B0   (OFF_A1 + BM * SA)         // 36864
#define OFF_B1   (OFF_B0 + 256 * SB)        // 73728
#define OFF_Z    (OFF_B1 + 256 * SB)        // 110592
#define OFF_MP   (OFF_Z + BM * SZ)          // 178176
#define OFF_P2   (OFF_MP + 1024)            // 179200
#define OFF_S2   (OFF_P2 + 1024)            // 180224 (row sumsq, 128 f32)
#define OFF_INV  (OFF_S2 + 512)             // 180736
#define OFF_Z2N  (OFF_INV + 512)            // 181248
#define SMEM_SZ  (OFF_Z2N + 512)            // 181760 bytes

__device__ float g_mproj[DP];                 // mean @ proj
__device__ float g_p2[CC];                    // ||p_c||^2
__device__ __nv_bfloat16 g_projT[DP * D_IN];  // [n][k] = proj[k][n], bf16
__device__ __nv_bfloat16 g_protosb[CC * DP];  // bf16 copy (already K-major)

// ---------------- helpers ----------------
__device__ __forceinline__ uint32_t smem_u32(const void* p) {
    uint32_t a;
    asm("{ .reg .u64 t; cvta.to.shared.u64 t, %1; cvt.u32.u64 %0, t; }" : "=r"(a) : "l"(p));
    return a;
}
__device__ __forceinline__ void ldsm4(uint32_t (&r)[4], uint32_t addr) {
    asm volatile("ldmatrix.sync.aligned.m8n8.x4.shared.b16 {%0,%1,%2,%3}, [%4];"
        : "=r"(r[0]), "=r"(r[1]), "=r"(r[2]), "=r"(r[3]) : "r"(addr));
}
__device__ __forceinline__ void mma16816(float (&d)[4], const uint32_t (&a)[4],
                                         uint32_t b0, uint32_t b1) {
    asm volatile("mma.sync.aligned.m16n8k16.row.col.f32.bf16.bf16.f32 "
        "{%0,%1,%2,%3},{%4,%5,%6,%7},{%8,%9},{%0,%1,%2,%3};"
        : "+f"(d[0]), "+f"(d[1]), "+f"(d[2]), "+f"(d[3])
        : "r"(a[0]), "r"(a[1]), "r"(a[2]), "r"(a[3]), "r"(b0), "r"(b1));
}

// ---------------- precompute kernels ----------------
__global__ void pre_convP(const float* __restrict__ proj) {   // [k][n] fp32 -> [n][k] bf16
    int i = blockIdx.x * 256 + threadIdx.x;                   // coalesced read over k*256+n
    int k = i >> 8, n = i & 255;
    g_projT[n * D_IN + k] = __float2bfloat16(proj[i]);
}
__global__ void pre_convC(const float* __restrict__ protos) {
    int i = blockIdx.x * 256 + threadIdx.x;
    g_protosb[i] = __float2bfloat16(protos[i]);
}
__global__ void pre_scalars(const float* __restrict__ mean,
                            const float* __restrict__ proj,
                            const float* __restrict__ protos) {
    // 64 blocks x 128 threads: warp g in [0,256) computes mproj[g] and p2[g]
    int g = blockIdx.x * 4 + (threadIdx.x >> 5);
    int lane = threadIdx.x & 31;
    float a = 0.f;
    for (int k = lane; k < D_IN; k += 32) a = fmaf(mean[k], proj[k * DP + g], a);
#pragma unroll
    for (int o = 16; o; o >>= 1) a += __shfl_xor_sync(~0u, a, o);
    if (!lane) g_mproj[g] = a;
    float s = 0.f;
    const float* p = protos + (size_t)g * DP;
    for (int d = lane; d < DP; d += 32) s = fmaf(p[d], p[d], s);
#pragma unroll
    for (int o = 16; o; o >>= 1) s += __shfl_xor_sync(~0u, s, o);
    if (!lane) g_p2[g] = s;
}

// ---------------- fused main kernel ----------------
__global__ void __launch_bounds__(NT, 1)
proto_mma(const float* __restrict__ X, float* __restrict__ out, int N) {
    extern __shared__ __align__(16) char smem[];
    const uint32_t sbase = smem_u32(smem);
    const int tid = threadIdx.x;
    const int wid = tid >> 5, lane = tid & 31;
    const int wm = wid & 1;          // 2 warps over M (64 rows each)
    const int wn = wid >> 1;         // 8 warps over N (32 cols each)
    const int rowBase = blockIdx.x * BM;

    if (tid < 256) {
        ((float*)(smem + OFF_MP))[tid] = g_mproj[tid];
        ((float*)(smem + OFF_P2))[tid] = g_p2[tid];
    }
    if (tid < BM) ((float*)(smem + OFF_S2))[tid] = 0.f;
    __syncthreads();

    float acc[4][4][4];
#pragma unroll
    for (int i = 0; i < 4; ++i)
#pragma unroll
        for (int j = 0; j < 4; ++j)
#pragma unroll
            for (int c = 0; c < 4; ++c) acc[i][j][c] = 0.f;

    // ---- tile loaders ----
    auto loadA = [&](int kb, char* dst) {   // X[128 rows][64 k] fp32 -> bf16, stride SA
#pragma unroll
        for (int ii = 0; ii < 4; ++ii) {
            int idx = tid + NT * ii;        // 2048 float4
            int r = idx >> 4, q = idx & 15;
            int gr = rowBase + r; if (gr >= N) gr = N - 1;
            float4 v = *(const float4*)(X + (size_t)gr * D_IN + kb * BK + q * 4);
            __nv_bfloat162 p0 = __floats2bfloat162_rn(v.x, v.y);
            __nv_bfloat162 p1 = __floats2bfloat162_rn(v.z, v.w);
            uint2 w; w.x = *(uint32_t*)&p0; w.y = *(uint32_t*)&p1;
            *(uint2*)(dst + r * SA + q * 8) = w;
        }
    };
    auto loadB = [&](const __nv_bfloat16* src, int srcStrideB, int kb, char* dst) {
#pragma unroll
        for (int ii = 0; ii < 4; ++ii) {    // 256 rows x 64 k bf16, stride SB
            int idx = tid + NT * ii;        // 2048 int4
            int n = idx >> 3, o = idx & 7;
            int4 v = *(const int4*)((const char*)src + (size_t)n * srcStrideB + kb * 128 + o * 16);
            *(int4*)(dst + n * SB + o * 16) = v;
        }
    };

    // ---- warp-tile compute over one 64-wide K chunk ----
    auto compute = [&](uint32_t aBase, uint32_t bBase, int strideA) {
        const int aRow = wm * 64 + (lane & 15);
        const int bRow = wn * 32 + (lane >> 4) * 8 + (lane & 7);
#pragma unroll
        for (int s = 0; s < 4; ++s) {       // 4 k-steps of 16
            const int aCol = s * 32 + (lane >> 4) * 16;
            const int bCol = s * 32 + ((lane >> 3) & 1) * 16;
            uint32_t af[4][4], bfr[2][4];
#pragma unroll
            for (int i = 0; i < 4; ++i)
                ldsm4(af[i], aBase + (uint32_t)((aRow + i * 16) * strideA + aCol));
#pragma unroll
            for (int jj = 0; jj < 2; ++jj)
                ldsm4(bfr[jj], bBase + (uint32_t)((bRow + jj * 16) * SB + bCol));
#pragma unroll
            for (int i = 0; i < 4; ++i)
#pragma unroll
                for (int jj = 0; jj < 2; ++jj) {
                    mma16816(acc[i][2 * jj],     af[i], bfr[jj][0], bfr[jj][1]);
                    mma16816(acc[i][2 * jj + 1], af[i], bfr[jj][2], bfr[jj][3]);
                }
        }
    };

    // ================= Phase 1: Z = Xbf16 @ projT^T =================
    loadA(0, smem + OFF_A0);
    loadB(g_projT, D_IN * 2, 0, smem + OFF_B0);
    __syncthreads();
    for (int kb = 0; kb < 16; ++kb) {
        uint32_t aCur = sbase + ((kb & 1) ? OFF_A1 : OFF_A0);
        uint32_t bCur = sbase + ((kb & 1) ? OFF_B1 : OFF_B0);
        if (kb < 15) {
            loadA(kb + 1, smem + ((kb & 1) ? OFF_A0 : OFF_A1));
            loadB(g_projT, D_IN * 2, kb + 1, smem + ((kb & 1) ? OFF_B0 : OFF_B1));
        }
        compute(aCur, bCur, SA);
        __syncthreads();
    }

    // ======== Epilogue 1: center, row sumsq, stash unnormalized z (bf16) ========
    {
        const float* mp = (const float*)(smem + OFF_MP);
        float* s2 = (float*)(smem + OFF_S2);
        char* Zb = smem + OFF_Z;
        const int r0 = wm * 64 + (lane >> 2);
        const int cq = (lane & 3) * 2;
#pragma unroll
        for (int i = 0; i < 4; ++i) {
#pragma unroll
            for (int h = 0; h < 2; ++h) {
                const int r = r0 + i * 16 + h * 8;
                float ss = 0.f;
#pragma unroll
                for (int j = 0; j < 4; ++j) {
                    const int col = wn * 32 + j * 8 + cq;
                    float z0 = acc[i][j][2 * h]     - mp[col];
                    float z1 = acc[i][j][2 * h + 1] - mp[col + 1];
                    ss = fmaf(z0, z0, fmaf(z1, z1, ss));
                    __nv_bfloat162 pz = __floats2bfloat162_rn(z0, z1);
                    *(uint32_t*)(Zb + r * SZ + col * 2) = *(uint32_t*)&pz;
                }
                ss += __shfl_xor_sync(~0u, ss, 1);
                ss += __shfl_xor_sync(~0u, ss, 2);
                if ((lane & 3) == 0) atomicAdd(&s2[r], ss);
            }
        }
    }
    __syncthreads();
    if (tid < BM) {
        float ss = ((float*)(smem + OFF_S2))[tid];
        float inv = 1.f / fmaxf(sqrtf(ss), 1e-12f);       // F.normalize eps
        ((float*)(smem + OFF_INV))[tid] = inv;
        ((float*)(smem + OFF_Z2N))[tid] = ss * inv * inv; // ||z_n||^2
    }
#pragma unroll
    for (int i = 0; i < 4; ++i)
#pragma unroll
        for (int j = 0; j < 4; ++j)
#pragma unroll
            for (int c = 0; c < 4; ++c) acc[i][j][c] = 0.f;
    __syncthreads();

    // ================= Phase 2: S = Zbf16 @ protos^T =================
    loadB(g_protosb, DP * 2, 0, smem + OFF_B0);
    __syncthreads();
    for (int kb = 0; kb < 4; ++kb) {
        uint32_t bCur = sbase + ((kb & 1) ? OFF_B1 : OFF_B0);
        if (kb < 3)
            loadB(g_protosb, DP * 2, kb + 1, smem + ((kb & 1) ? OFF_B0 : OFF_B1));
        compute(sbase + OFF_Z + kb * 128, bCur, SZ);   // A = Z, k-offset 64 cols = 128B
        __syncthreads();
    }

    // ======== Final epilogue: score = -sqrt(max(z2n + p2 - 2*inv*S, 0)) ========
    {
        const float* p2 = (const float*)(smem + OFF_P2);
        const float* invA = (const float*)(smem + OFF_INV);
        const float* z2A = (const float*)(smem + OFF_Z2N);
        const int r0 = wm * 64 + (lane >> 2);
        const int cq = (lane & 3) * 2;
#pragma unroll
        for (int i = 0; i < 4; ++i) {
#pragma unroll
            for (int h = 0; h < 2; ++h) {
                const int r = r0 + i * 16 + h * 8;
                const int row = rowBase + r;
                if (row >= N) continue;
                const float m2 = -2.f * invA[r];
                const float z2n = z2A[r];
                float* orow = out + (size_t)row * CC;
#pragma unroll
                for (int j = 0; j < 4; ++j) {
                    const int col = wn * 32 + j * 8 + cq;
                    float d0 = fmaf(m2, acc[i][j][2 * h],     z2n + p2[col]);
                    float d1 = fmaf(m2, acc[i][j][2 * h + 1], z2n + p2[col + 1]);
                    float2 v;
                    v.x = -sqrtf(fmaxf(d0, 0.f));
                    v.y = -sqrtf(fmaxf(d1, 0.f));
                    *(float2*)(orow + col) = v;
                }
            }
        }
    }
}

extern "C" void kernel_launch(void* const* d_in, const int* in_sizes, int n_in,
                              void* d_out, int out_size) {
    const float* X      = (const float*)d_in[0];
    const float* mean   = (const float*)d_in[1];
    const float* proj   = (const float*)d_in[2];
    const float* protos = (const float*)d_in[3];
    float* out = (float*)d_out;

    const int Din = in_sizes[1];           // 1024
    const int N   = in_sizes[0] / Din;     // 32768

    static bool attr_set = false;
    if (!attr_set) {
        cudaFuncSetAttribute(proto_mma, cudaFuncAttributeMaxDynamicSharedMemorySize, SMEM_SZ);
        attr_set = true;
    }

    pre_convP<<<(D_IN * DP) / 256, 256>>>(proj);
    pre_convC<<<(CC * DP) / 256, 256>>>(protos);
    pre_scalars<<<64, 128>>>(mean, proj, protos);
    proto_mma<<<(N + BM - 1) / BM, NT, SMEM_SZ>>>(X, out, N);
}

// round 9
// speedup vs baseline: 6.2216x; 1.3149x over previous
#include <cuda_runtime.h>
#include <cuda_bf16.h>
#include <cstdint>

#define D_IN 1024
#define DP   256
#define CC   256
#define BM   128
#define BK   64
#define NT   256

// padded SMEM row strides (bytes) -> conflict-free ldmatrix without XOR swizzle
#define SA 144    // A/B tiles: 64 bf16 = 128B + 16B pad   (144/4 = 36 ≡ 4 mod 32)
#define SB 144
#define SZ 528    // Z rows: 256 bf16 = 512B + 16B pad     (528/4 = 132 ≡ 4 mod 32)

// smem layout (byte offsets)
#define OFF_A0   0
#define OFF_A1   (OFF_A0 + BM * SA)         // 18432
#define OFF_B0   (OFF_A1 + BM * SA)         // 36864
#define OFF_B1   (OFF_B0 + 256 * SB)        // 73728
#define OFF_Z    (OFF_B1 + 256 * SB)        // 110592
#define OFF_MP   (OFF_Z + BM * SZ)          // 178176
#define OFF_P2   (OFF_MP + 1024)            // 179200
#define OFF_S2   (OFF_P2 + 1024)            // 180224 (row sumsq, 128 f32)
#define OFF_INV  (OFF_S2 + 512)             // 180736
#define OFF_Z2N  (OFF_INV + 512)            // 181248
#define SMEM_SZ  (OFF_Z2N + 512)            // 181760 bytes

__device__ float g_mproj[DP];                 // mean @ proj
__device__ float g_p2[CC];                    // ||p_c||^2
__device__ __nv_bfloat16 g_projT[DP * D_IN];  // [n][k] = proj[k][n], bf16
__device__ __nv_bfloat16 g_protosb[CC * DP];  // bf16 copy (already K-major)

// ---------------- helpers ----------------
__device__ __forceinline__ uint32_t smem_u32(const void* p) {
    uint32_t a;
    asm("{ .reg .u64 t; cvta.to.shared.u64 t, %1; cvt.u32.u64 %0, t; }" : "=r"(a) : "l"(p));
    return a;
}
__device__ __forceinline__ void ldsm4(uint32_t (&r)[4], uint32_t addr) {
    asm volatile("ldmatrix.sync.aligned.m8n8.x4.shared.b16 {%0,%1,%2,%3}, [%4];"
        : "=r"(r[0]), "=r"(r[1]), "=r"(r[2]), "=r"(r[3]) : "r"(addr));
}
__device__ __forceinline__ void mma16816(float (&d)[4], const uint32_t (&a)[4],
                                         uint32_t b0, uint32_t b1) {
    asm volatile("mma.sync.aligned.m16n8k16.row.col.f32.bf16.bf16.f32 "
        "{%0,%1,%2,%3},{%4,%5,%6,%7},{%8,%9},{%0,%1,%2,%3};"
        : "+f"(d[0]), "+f"(d[1]), "+f"(d[2]), "+f"(d[3])
        : "r"(a[0]), "r"(a[1]), "r"(a[2]), "r"(a[3]), "r"(b0), "r"(b1));
}
__device__ __forceinline__ void cp16(uint32_t dst, const void* src) {
    asm volatile("cp.async.cg.shared.global [%0], [%1], 16;" :: "r"(dst), "l"(src) : "memory");
}
#define CP_COMMIT() asm volatile("cp.async.commit_group;" ::: "memory")
#define CP_WAIT0()  asm volatile("cp.async.wait_group 0;" ::: "memory")

// ---------------- precompute kernels ----------------
__global__ void pre_convP(const float* __restrict__ proj) {   // [k][n] fp32 -> [n][k] bf16
    int i = blockIdx.x * 256 + threadIdx.x;
    int k = i >> 8, n = i & 255;
    g_projT[n * D_IN + k] = __float2bfloat16(proj[i]);
}
__global__ void pre_convC(const float* __restrict__ protos) {
    int i = blockIdx.x * 256 + threadIdx.x;
    g_protosb[i] = __float2bfloat16(protos[i]);
}
__global__ void pre_scalars(const float* __restrict__ mean,
                            const float* __restrict__ proj,
                            const float* __restrict__ protos) {
    int g = blockIdx.x * 4 + (threadIdx.x >> 5);
    int lane = threadIdx.x & 31;
    float a = 0.f;
    for (int k = lane; k < D_IN; k += 32) a = fmaf(mean[k], proj[k * DP + g], a);
#pragma unroll
    for (int o = 16; o; o >>= 1) a += __shfl_xor_sync(~0u, a, o);
    if (!lane) g_mproj[g] = a;
    float s = 0.f;
    const float* p = protos + (size_t)g * DP;
    for (int d = lane; d < DP; d += 32) s = fmaf(p[d], p[d], s);
#pragma unroll
    for (int o = 16; o; o >>= 1) s += __shfl_xor_sync(~0u, s, o);
    if (!lane) g_p2[g] = s;
}

// ---------------- fused main kernel ----------------
__global__ void __launch_bounds__(NT, 1)
proto_mma(const float* __restrict__ X, float* __restrict__ out, int N) {
    extern __shared__ __align__(16) char smem[];
    const uint32_t sbase = smem_u32(smem);
    const int tid = threadIdx.x;
    const int wid = tid >> 5, lane = tid & 31;
    const int wm = wid & 1;          // 2 warps over M (64 rows each)
    const int wn = wid >> 1;         // 4 warps over N (64 cols each)
    const int rowBase = blockIdx.x * BM;

    if (tid < 256) {
        ((float*)(smem + OFF_MP))[tid] = g_mproj[tid];
        ((float*)(smem + OFF_P2))[tid] = g_p2[tid];
    }
    if (tid < BM) ((float*)(smem + OFF_S2))[tid] = 0.f;
    __syncthreads();

    float acc[4][8][4];
#pragma unroll
    for (int i = 0; i < 4; ++i)
#pragma unroll
        for (int j = 0; j < 8; ++j)
#pragma unroll
            for (int c = 0; c < 4; ++c) acc[i][j][c] = 0.f;

    // ---- A tile: split issue / store (32 staging regs) ----
    float4 av[8];
    auto loadA_issue = [&](int kb) {
#pragma unroll
        for (int ii = 0; ii < 8; ++ii) {
            int idx = tid + NT * ii;        // 2048 float4
            int r = idx >> 4, q = idx & 15;
            int gr = rowBase + r; if (gr >= N) gr = N - 1;
            av[ii] = *(const float4*)(X + (size_t)gr * D_IN + kb * BK + q * 4);
        }
    };
    auto storeA = [&](char* dst) {
#pragma unroll
        for (int ii = 0; ii < 8; ++ii) {
            int idx = tid + NT * ii;
            int r = idx >> 4, q = idx & 15;
            __nv_bfloat162 p0 = __floats2bfloat162_rn(av[ii].x, av[ii].y);
            __nv_bfloat162 p1 = __floats2bfloat162_rn(av[ii].z, av[ii].w);
            uint2 w; w.x = *(uint32_t*)&p0; w.y = *(uint32_t*)&p1;
            *(uint2*)(dst + r * SA + q * 8) = w;
        }
    };
    // ---- B tile via cp.async (bf16 global -> smem, no regs) ----
    auto cpB = [&](const __nv_bfloat16* src, size_t strideB, int kb, uint32_t dstOff) {
#pragma unroll
        for (int ii = 0; ii < 8; ++ii) {
            int idx = tid + NT * ii;        // 2048 x 16B
            int n = idx >> 3, o = idx & 7;
            cp16(sbase + dstOff + (uint32_t)(n * SB + o * 16),
                 (const char*)src + (size_t)n * strideB + (size_t)kb * 128 + o * 16);
        }
    };

    // ---- warp-tile compute (64x64) over one 64-wide K chunk ----
    auto compute = [&](uint32_t aBase, uint32_t bBase, int strideA) {
        const int aRow = wm * 64 + (lane & 15);
        const int bRowBase = wn * 64 + (lane >> 4) * 8 + (lane & 7);
#pragma unroll
        for (int s = 0; s < 4; ++s) {       // 4 k-steps of 16
            const int aCol = s * 32 + (lane >> 4) * 16;            // bytes
            const int bCol = s * 32 + ((lane >> 3) & 1) * 16;      // bytes
            uint32_t af[4][4], bfr[4][4];
#pragma unroll
            for (int i = 0; i < 4; ++i)
                ldsm4(af[i], aBase + (uint32_t)((aRow + i * 16) * strideA + aCol));
#pragma unroll
            for (int jj = 0; jj < 4; ++jj)
                ldsm4(bfr[jj], bBase + (uint32_t)((bRowBase + jj * 16) * SB + bCol));
#pragma unroll
            for (int i = 0; i < 4; ++i)
#pragma unroll
                for (int jj = 0; jj < 4; ++jj) {
                    mma16816(acc[i][2 * jj],     af[i], bfr[jj][0], bfr[jj][1]);
                    mma16816(acc[i][2 * jj + 1], af[i], bfr[jj][2], bfr[jj][3]);
                }
        }
    };

    // ================= Phase 1: Z = Xbf16 @ projT^T =================
    loadA_issue(0);
    cpB(g_projT, D_IN * 2, 0, OFF_B0);
    CP_COMMIT();
    storeA(smem + OFF_A0);
    CP_WAIT0();
    __syncthreads();
    for (int kb = 0; kb < 16; ++kb) {
        uint32_t aCur = sbase + ((kb & 1) ? OFF_A1 : OFF_A0);
        uint32_t bCur = sbase + ((kb & 1) ? OFF_B1 : OFF_B0);
        if (kb < 15) {
            loadA_issue(kb + 1);                                   // LDGs in flight
            cpB(g_projT, D_IN * 2, kb + 1, (kb & 1) ? OFF_B0 : OFF_B1);
            CP_COMMIT();
        }
        compute(aCur, bCur, SA);                                   // hides the LDG latency
        if (kb < 15) {
            storeA(smem + ((kb & 1) ? OFF_A0 : OFF_A1));
            CP_WAIT0();
        }
        __syncthreads();
    }

    // prefetch protos chunk 0 into B0 (free after kb=15 which used B1), overlap epilogue
    cpB(g_protosb, DP * 2, 0, OFF_B0);
    CP_COMMIT();

    // ======== Epilogue 1: center, row sumsq, stash unnormalized z (bf16) ========
    {
        const float* mp = (const float*)(smem + OFF_MP);
        float* s2 = (float*)(smem + OFF_S2);
        char* Zb = smem + OFF_Z;
        const int r0 = wm * 64 + (lane >> 2);
        const int cq = (lane & 3) * 2;
#pragma unroll
        for (int i = 0; i < 4; ++i) {
#pragma unroll
            for (int h = 0; h < 2; ++h) {
                const int r = r0 + i * 16 + h * 8;
                float ss = 0.f;
#pragma unroll
                for (int j = 0; j < 8; ++j) {
                    const int col = wn * 64 + j * 8 + cq;
                    float z0 = acc[i][j][2 * h]     - mp[col];
                    float z1 = acc[i][j][2 * h + 1] - mp[col + 1];
                    ss = fmaf(z0, z0, fmaf(z1, z1, ss));
                    __nv_bfloat162 pz = __floats2bfloat162_rn(z0, z1);
                    *(uint32_t*)(Zb + r * SZ + col * 2) = *(uint32_t*)&pz;
                }
                ss += __shfl_xor_sync(~0u, ss, 1);
                ss += __shfl_xor_sync(~0u, ss, 2);
                if ((lane & 3) == 0) atomicAdd(&s2[r], ss);
            }
        }
    }
    __syncthreads();
    if (tid < BM) {
        float ss = ((float*)(smem + OFF_S2))[tid];
        float inv = 1.f / fmaxf(sqrtf(ss), 1e-12f);       // F.normalize eps
        ((float*)(smem + OFF_INV))[tid] = inv;
        ((float*)(smem + OFF_Z2N))[tid] = ss * inv * inv; // ||z_n||^2
    }
#pragma unroll
    for (int i = 0; i < 4; ++i)
#pragma unroll
        for (int j = 0; j < 8; ++j)
#pragma unroll
            for (int c = 0; c < 4; ++c) acc[i][j][c] = 0.f;
    CP_WAIT0();
    __syncthreads();

    // ================= Phase 2: S = Zbf16 @ protos^T =================
    for (int kb = 0; kb < 4; ++kb) {
        uint32_t bCur = sbase + ((kb & 1) ? OFF_B1 : OFF_B0);
        if (kb < 3) {
            cpB(g_protosb, DP * 2, kb + 1, (kb & 1) ? OFF_B0 : OFF_B1);
            CP_COMMIT();
        }
        compute(sbase + OFF_Z + kb * 128, bCur, SZ);   // A = Z, k-offset 64 cols = 128B
        if (kb < 3) CP_WAIT0();
        __syncthreads();
    }

    // ======== Final epilogue: score = -sqrt(max(z2n + p2 - 2*inv*S, 0)) ========
    {
        const float* p2 = (const float*)(smem + OFF_P2);
        const float* invA = (const float*)(smem + OFF_INV);
        const float* z2A = (const float*)(smem + OFF_Z2N);
        const int r0 = wm * 64 + (lane >> 2);
        const int cq = (lane & 3) * 2;
#pragma unroll
        for (int i = 0; i < 4; ++i) {
#pragma unroll
            for (int h = 0; h < 2; ++h) {
                const int r = r0 + i * 16 + h * 8;
                const int row = rowBase + r;
                if (row >= N) continue;
                const float m2 = -2.f * invA[r];
                const float z2n = z2A[r];
                float* orow = out + (size_t)row * CC;
#pragma unroll
                for (int j = 0; j < 8; ++j) {
                    const int col = wn * 64 + j * 8 + cq;
                    float d0 = fmaf(m2, acc[i][j][2 * h],     z2n + p2[col]);
                    float d1 = fmaf(m2, acc[i][j][2 * h + 1], z2n + p2[col + 1]);
                    float2 v;
                    v.x = -sqrtf(fmaxf(d0, 0.f));
                    v.y = -sqrtf(fmaxf(d1, 0.f));
                    *(float2*)(orow + col) = v;
                }
            }
        }
    }
}

extern "C" void kernel_launch(void* const* d_in, const int* in_sizes, int n_in,
                              void* d_out, int out_size) {
    const float* X      = (const float*)d_in[0];
    const float* mean   = (const float*)d_in[1];
    const float* proj   = (const float*)d_in[2];
    const float* protos = (const float*)d_in[3];
    float* out = (float*)d_out;

    const int Din = in_sizes[1];           // 1024
    const int N   = in_sizes[0] / Din;     // 32768

    static bool attr_set = false;
    if (!attr_set) {
        cudaFuncSetAttribute(proto_mma, cudaFuncAttributeMaxDynamicSharedMemorySize, SMEM_SZ);
        attr_set = true;
    }

    pre_convP<<<(D_IN * DP) / 256, 256>>>(proj);
    pre_convC<<<(CC * DP) / 256, 256>>>(protos);
    pre_scalars<<<64, 128>>>(mean, proj, protos);
    proto_mma<<<(N + BM - 1) / BM, NT, SMEM_SZ>>>(X, out, N);
}